// round 2
// baseline (speedup 1.0000x reference)
#include <cuda_runtime.h>

// PosMLP: per-query generated tiny MLP over a 48x48 grid.
// out[b,q,h,w] = b2 + sum_k relu(ty_k[h] + tx_k[w]) * w2_k
// Using relu(u) = (u+|u|)/2:
//   out = b2 + Sy[h] + Sx[w] + sum_k |ty_k[h]+tx_k[w]| * (w2_k/2)
// with Sy[h] = 0.5*sum_k ty_k[h]*w2_k, Sx[w] = 0.5*sum_k tx_k[w]*w2_k (separable).
// |t| is a free FFMA operand modifier -> 2 fp ops per element per k.

constexpr int C_DIM = 256;       // query channels
constexpr int HD    = 16;        // hidden dim
constexpr int NW    = 4*HD + 1;  // 65 generated weights per query
constexpr int GH    = 48;
constexpr int GW    = 48;
constexpr int TPB   = 144;       // one 4x4 output tile per thread (12x12 tiles)

__global__ __launch_bounds__(TPB)
void posmlp_kernel(const float* __restrict__ queries,
                   const float* __restrict__ pos,
                   const float* __restrict__ w_gen,
                   const float* __restrict__ b_gen,
                   float* __restrict__ out)
{
    __shared__ __align__(16) float s_q[C_DIM];
    __shared__ float s_w[NW];
    __shared__ __align__(16) float s_ty[HD][GH];  // ty[k][h] = rel_y[h]*w1y[k] + b1[k]
    __shared__ __align__(16) float s_tx[HD][GW];  // tx[k][w] = rel_x[w]*w1x[k]
    __shared__ __align__(16) float s_sy[GH];      // 0.5*sum_k ty[k][h]*w2[k]
    __shared__ __align__(16) float s_sxb[GW];     // 0.5*sum_k tx[k][w]*w2[k] + b2

    const int bq   = blockIdx.x;
    const int tid  = threadIdx.x;
    const int warp = tid >> 5;
    const int lane = tid & 31;

    // ---- Phase 0: stage query row (coalesced) ----
    for (int c = tid; c < C_DIM; c += TPB)
        s_q[c] = queries[(size_t)bq * C_DIM + c];
    __syncthreads();

    // ---- Phase 1: weights[n] = dot(q, w_gen[n]) + b_gen[n]; warps 0-3, float4 ----
    if (warp < 4) {
        const float4* q4 = reinterpret_cast<const float4*>(s_q);
        for (int n = warp; n < NW; n += 4) {
            const float4* w4 = reinterpret_cast<const float4*>(w_gen + n * C_DIM);
            float s = 0.f;
            #pragma unroll
            for (int j = 0; j < 2; ++j) {
                int c = lane + 32 * j;
                float4 wv = w4[c];
                float4 qv = q4[c];
                s = fmaf(wv.x, qv.x, s);
                s = fmaf(wv.y, qv.y, s);
                s = fmaf(wv.z, qv.z, s);
                s = fmaf(wv.w, qv.w, s);
            }
            #pragma unroll
            for (int off = 16; off; off >>= 1)
                s += __shfl_xor_sync(0xffffffffu, s, off);
            if (lane == 0) s_w[n] = s + b_gen[n];
        }
    }
    __syncthreads();

    // ---- Phase 2: separable tables (GH==GW so one fused loop) ----
    {
        const float cx = pos[bq*4 + 0];
        const float cy = pos[bq*4 + 1];
        const float inv_bw = 1.0f / pos[bq*4 + 2];
        const float inv_bh = 1.0f / pos[bq*4 + 3];
        for (int i = tid; i < HD * GH; i += TPB) {
            int k = i / GH, g = i % GH;
            float gc = ((float)g + 0.5f) * (1.0f / (float)GH);
            float rel_y = (gc - cy) * inv_bh;
            float rel_x = (gc - cx) * inv_bw;
            s_ty[k][g] = fmaf(rel_y, s_w[2*k], s_w[2*HD + k]);
            s_tx[k][g] = rel_x * s_w[2*k + 1];
        }
    }
    __syncthreads();

    // ---- Phase 2b: Sy / Sx separable sums ----
    if (tid < 2 * GH) {
        const bool isX = (tid >= GH);
        const int  idx = isX ? tid - GH : tid;
        float s = 0.f;
        #pragma unroll
        for (int k = 0; k < HD; ++k) {
            float w2h = 0.5f * s_w[3*HD + k];
            float v   = isX ? s_tx[k][idx] : s_ty[k][idx];
            s = fmaf(v, w2h, s);
        }
        if (isX) s_sxb[idx] = s + s_w[4*HD];
        else     s_sy[idx]  = s;
    }
    __syncthreads();

    // ---- Phase 3: 4x4 register tile per thread ----
    float w2h[HD];
    #pragma unroll
    for (int k = 0; k < HD; ++k) w2h[k] = 0.5f * s_w[3*HD + k];

    const int h0 = (tid / 12) * 4;
    const int w0 = (tid % 12) * 4;

    float acc[4][4];
    #pragma unroll
    for (int i = 0; i < 4; ++i)
        #pragma unroll
        for (int j = 0; j < 4; ++j) acc[i][j] = 0.f;

    #pragma unroll
    for (int k = 0; k < HD; ++k) {
        float4 a4 = *reinterpret_cast<const float4*>(&s_ty[k][h0]);  // LDS.128
        float4 b4 = *reinterpret_cast<const float4*>(&s_tx[k][w0]);  // LDS.128
        float av[4] = {a4.x, a4.y, a4.z, a4.w};
        float bv[4] = {b4.x, b4.y, b4.z, b4.w};
        #pragma unroll
        for (int i = 0; i < 4; ++i)
            #pragma unroll
            for (int j = 0; j < 4; ++j) {
                float t = av[i] + bv[j];                      // FADD
                acc[i][j] = fmaf(fabsf(t), w2h[k], acc[i][j]); // FFMA with |t|
            }
    }

    // ---- Epilogue: add separable terms, STG.128 per row ----
    float4 sy4 = *reinterpret_cast<const float4*>(&s_sy[h0]);
    float4 sx4 = *reinterpret_cast<const float4*>(&s_sxb[w0]);
    float syv[4] = {sy4.x, sy4.y, sy4.z, sy4.w};
    float sxv[4] = {sx4.x, sx4.y, sx4.z, sx4.w};

    float* outp = out + (size_t)bq * (GH * GW);
    #pragma unroll
    for (int i = 0; i < 4; ++i) {
        float base = syv[i];
        float4 r;
        r.x = acc[i][0] + (base + sxv[0]);
        r.y = acc[i][1] + (base + sxv[1]);
        r.z = acc[i][2] + (base + sxv[2]);
        r.w = acc[i][3] + (base + sxv[3]);
        *reinterpret_cast<float4*>(&outp[(h0 + i) * GW + w0]) = r;
    }
}

extern "C" void kernel_launch(void* const* d_in, const int* in_sizes, int n_in,
                              void* d_out, int out_size)
{
    const float* queries = (const float*)d_in[0];
    const float* pos     = (const float*)d_in[1];
    const float* w_gen   = (const float*)d_in[2];
    const float* b_gen   = (const float*)d_in[3];
    float* out = (float*)d_out;

    int BQ = in_sizes[0] / C_DIM;  // B*Q = 1800
    posmlp_kernel<<<BQ, TPB>>>(queries, pos, w_gen, b_gen, out);
}